// round 7
// baseline (speedup 1.0000x reference)
#include <cuda_runtime.h>
#include <stdint.h>

// ---------------------------------------------------------------------------
// DynamicPointConvBackBone fused kernel, register-tiled split-K edition.
// 512 threads = 2 groups x 256; group g computes K-range [g*864,(g+1)*864).
// Thread micro-tile: 4 rows x 8 cols (cols cb*4..+3 and 64+cb*4..+3).
// Warp covers 8 full rows x 128 cols -> shuffle-only LayerNorm.
// Group 1 spills partials to smem; group 0 reduces + LN + ReLU + coords.
// ---------------------------------------------------------------------------

#define K3      27
#define CIN     64
#define COUT    128
#define KP      2048
#define KP_LOG2 11
#define TR      64         // rows per CTA
#define NT      512        // 2 groups x 256
#define KC      16         // K-values per chunk (quarter neighbor)
#define NCHG    54         // chunks per group (54*16 = 864)
#define AS      68         // A k-row stride in floats (64 + 4 pad, mult of 4)
#define EPS     1e-3f

typedef unsigned long long ull;

#define FFMA2(d, a, b) \
    asm("fma.rn.f32x2 %0, %1, %2, %0;" : "+l"(d) : "l"(a), "l"(b))
#define FADD2(d, a) \
    asm("add.rn.f32x2 %0, %0, %1;" : "+l"(d) : "l"(a))
#define PACK2(d, s) \
    asm("mov.b64 %0, {%1, %1};" : "=l"(d) : "f"(s))
#define BARG(gid) \
    asm volatile("bar.sync %0, 256;" :: "r"((gid) + 1) : "memory")

__device__ __forceinline__ float2 unpack_f32x2(ull v) {
    float2 f;
    asm("mov.b64 {%0, %1}, %2;" : "=f"(f.x), "=f"(f.y) : "l"(v));
    return f;
}

__global__ __launch_bounds__(NT, 1)
void fused_gather_gemm_ln(const float* __restrict__ feat,
                          const int* __restrict__ vidx,
                          const float* __restrict__ W,
                          const float* __restrict__ gamma,
                          const float* __restrict__ beta,
                          const int* __restrict__ num_list,
                          const float* __restrict__ cc,
                          float* __restrict__ out_feat,
                          float* __restrict__ out_coor,
                          int Nfeat, int M, int B, int totalRows)
{
    // pool: A bufs 2*(16*68)=2176 f + B bufs 2*(16*128)=4096 f = 6272 f
    // reduction spill needs 64*128 = 8192 f -> pool sized 8192 f (32KB)
    __shared__ float pool[TR * COUT];
    __shared__ int   idx_s[TR * K3];
    __shared__ int   src_s[TR];
    __shared__ int   val_s[TR];
    __shared__ int   nl_s[8];

    const int tid  = threadIdx.x;
    const int gid  = tid >> 8;          // group 0/1
    const int ltid = tid & 255;
    const int base = blockIdx.x * TR;

    float* const Ag = pool + gid * (KC * AS);
    float* const Bg = pool + 2 * (KC * AS) + gid * (KC * COUT);

    if (tid == 0) {
        #pragma unroll 4
        for (int i = 0; i < B && i < 8; ++i) nl_s[i] = num_list[i];
    }
    __syncthreads();

    // --- per-row source voxel + validity -----------------------------------
    if (tid < TR) {
        int gr = base + tid;
        int src = 0, valid = 0;
        if (gr < totalRows) {
            int b = gr >> KP_LOG2;
            int j = gr & (KP - 1);
            int off = 0;
            #pragma unroll 4
            for (int i = 0; i < b; ++i) off += nl_s[i];
            int nl = nl_s[b];
            src = off + j;
            if (src > M - 1) src = M - 1;
            if (src < 0)     src = 0;
            valid = (j < nl) ? 1 : 0;
        }
        src_s[tid] = src;
        val_s[tid] = valid;
    }
    __syncthreads();

    // --- neighbor indices (int32; neg -> -1 sentinel) ----------------------
    {
        int r  = tid >> 3;                 // 0..63
        int k0 = (tid & 7) * 4;            // 0,4,...,28
        int k1 = (k0 == 24) ? K3 : k0 + 4;
        if (k0 < K3) {
            const int* row = vidx + (size_t)src_s[r] * K3;
            for (int k = k0; k < k1; ++k) {
                int raw = row[k];
                int v = raw;
                if (raw < 0) v = -1;
                else if (v > Nfeat - 1) v = Nfeat - 1;
                idx_s[r * K3 + k] = v;
            }
        }
    }
    __syncthreads();

    // --- accumulators: 4 rows x 8 cols per thread (4x4 f32x2) ---------------
    ull acc[4][4];
    #pragma unroll
    for (int j = 0; j < 4; ++j)
        #pragma unroll
        for (int p = 0; p < 4; ++p) acc[j][p] = 0ull;

    const int gw   = (tid >> 5) & 7;     // warp in group -> rows gw*8..+7
    const int lane = tid & 31;
    const int rb   = lane >> 4;          // row-block 0/1 (4 rows each)
    const int cb   = lane & 15;          // col-block -> cols cb*4 and 64+cb*4
    const int row0 = gw * 8 + rb * 4;    // first of this thread's 4 rows

    // gather mapping: 4 lanes per row (float4 channel groups)
    const int g_grp = ltid & 3;          // k_local group (4 consecutive k)
    const int g_row = ltid >> 2;         // row 0..63

    float4 wreg[2];
    float4 areg;

    // prologue: prefetch chunk 0 of this group
    {
        int C = gid * NCHG;
        int n = C >> 2, q = C & 3;
        const float4* Wg = (const float4*)(W + (size_t)(n * CIN + q * KC) * COUT);
        wreg[0] = Wg[ltid];
        wreg[1] = Wg[ltid + 256];
        int fid = idx_s[g_row * K3 + n];
        areg = (fid >= 0)
            ? ((const float4*)(feat + (size_t)fid * CIN))[q * 4 + g_grp]
            : make_float4(0.f, 0.f, 0.f, 0.f);
    }

    for (int c = 0; c < NCHG; ++c) {
        BARG(gid);   // previous compute done reading this group's buffers

        // fill smem from prefetch regs
        {
            float4* Bv = (float4*)Bg;
            Bv[ltid]       = wreg[0];
            Bv[ltid + 256] = wreg[1];
            // A k-major scalar: A[k_local][row], k_local = g_grp*4 + i
            float* a0 = Ag + (g_grp * 4) * AS + g_row;
            a0[0 * AS] = areg.x;
            a0[1 * AS] = areg.y;
            a0[2 * AS] = areg.z;
            a0[3 * AS] = areg.w;
        }
        BARG(gid);   // buffers ready

        // prefetch chunk c+1
        if (c + 1 < NCHG) {
            int C = gid * NCHG + c + 1;
            int n = C >> 2, q = C & 3;
            const float4* Wg = (const float4*)(W + (size_t)(n * CIN + q * KC) * COUT);
            wreg[0] = Wg[ltid];
            wreg[1] = Wg[ltid + 256];
            int fid = idx_s[g_row * K3 + n];
            areg = (fid >= 0)
                ? ((const float4*)(feat + (size_t)fid * CIN))[q * 4 + g_grp]
                : make_float4(0.f, 0.f, 0.f, 0.f);
        }

        // compute chunk: 16 K-steps, outer-product 4x8 per thread
        #pragma unroll
        for (int k = 0; k < KC; ++k) {
            float4 a4 = *(const float4*)(Ag + k * AS + row0);
            ulonglong2 bx = *(const ulonglong2*)(Bg + k * COUT + cb * 4);
            ulonglong2 by = *(const ulonglong2*)(Bg + k * COUT + 64 + cb * 4);
            ull pa;
            PACK2(pa, a4.x);
            FFMA2(acc[0][0], pa, bx.x); FFMA2(acc[0][1], pa, bx.y);
            FFMA2(acc[0][2], pa, by.x); FFMA2(acc[0][3], pa, by.y);
            PACK2(pa, a4.y);
            FFMA2(acc[1][0], pa, bx.x); FFMA2(acc[1][1], pa, bx.y);
            FFMA2(acc[1][2], pa, by.x); FFMA2(acc[1][3], pa, by.y);
            PACK2(pa, a4.z);
            FFMA2(acc[2][0], pa, bx.x); FFMA2(acc[2][1], pa, bx.y);
            FFMA2(acc[2][2], pa, by.x); FFMA2(acc[2][3], pa, by.y);
            PACK2(pa, a4.w);
            FFMA2(acc[3][0], pa, bx.x); FFMA2(acc[3][1], pa, bx.y);
            FFMA2(acc[3][2], pa, by.x); FFMA2(acc[3][3], pa, by.y);
        }
    }

    // --- cross-group reduction: group1 spills, group0 adds ------------------
    __syncthreads();                     // all buffers dead; pool becomes Red
    float* const Red = pool;             // 64 x 128
    if (gid == 1) {
        #pragma unroll
        for (int j = 0; j < 4; ++j) {
            int r = row0 + j;
            ulonglong2 v0; v0.x = acc[j][0]; v0.y = acc[j][1];
            ulonglong2 v1; v1.x = acc[j][2]; v1.y = acc[j][3];
            *(ulonglong2*)(Red + r * COUT + cb * 4)      = v0;
            *(ulonglong2*)(Red + r * COUT + 64 + cb * 4) = v1;
        }
    }
    __syncthreads();

    if (gid == 0) {
        #pragma unroll
        for (int j = 0; j < 4; ++j) {
            int r = row0 + j;
            ulonglong2 v0 = *(const ulonglong2*)(Red + r * COUT + cb * 4);
            ulonglong2 v1 = *(const ulonglong2*)(Red + r * COUT + 64 + cb * 4);
            FADD2(acc[j][0], v0.x); FADD2(acc[j][1], v0.y);
            FADD2(acc[j][2], v1.x); FADD2(acc[j][3], v1.y);
        }

        // --- LayerNorm + ReLU (reduce over 16 lanes sharing rb) -------------
        float4 g0 = ((const float4*)gamma)[cb];
        float4 g1 = ((const float4*)gamma)[16 + cb];
        float4 b0 = ((const float4*)beta)[cb];
        float4 b1 = ((const float4*)beta)[16 + cb];
        #pragma unroll
        for (int j = 0; j < 4; ++j) {
            float2 q0 = unpack_f32x2(acc[j][0]);
            float2 q1 = unpack_f32x2(acc[j][1]);
            float2 q2 = unpack_f32x2(acc[j][2]);
            float2 q3 = unpack_f32x2(acc[j][3]);
            float s  = (q0.x + q0.y) + (q1.x + q1.y)
                     + (q2.x + q2.y) + (q3.x + q3.y);
            float sq = q0.x*q0.x + q0.y*q0.y + q1.x*q1.x + q1.y*q1.y
                     + q2.x*q2.x + q2.y*q2.y + q3.x*q3.x + q3.y*q3.y;
            #pragma unroll
            for (int o = 8; o > 0; o >>= 1) {        // within 16-lane half
                s  += __shfl_xor_sync(0xffffffffu, s,  o);
                sq += __shfl_xor_sync(0xffffffffu, sq, o);
            }
            float mu  = s * (1.f / COUT);
            float var = sq * (1.f / COUT) - mu * mu;
            float inv = rsqrtf(var + EPS);
            int rl = row0 + j;
            int gr = base + rl;
            if (gr < totalRows) {
                float4 oa, ob;
                oa.x = fmaxf(0.f, (q0.x - mu) * inv * g0.x + b0.x);
                oa.y = fmaxf(0.f, (q0.y - mu) * inv * g0.y + b0.y);
                oa.z = fmaxf(0.f, (q1.x - mu) * inv * g0.z + b0.z);
                oa.w = fmaxf(0.f, (q1.y - mu) * inv * g0.w + b0.w);
                ob.x = fmaxf(0.f, (q2.x - mu) * inv * g1.x + b1.x);
                ob.y = fmaxf(0.f, (q2.y - mu) * inv * g1.y + b1.y);
                ob.z = fmaxf(0.f, (q3.x - mu) * inv * g1.z + b1.z);
                ob.w = fmaxf(0.f, (q3.y - mu) * inv * g1.w + b1.w);
                if (!val_s[rl]) {
                    oa = make_float4(0.f, 0.f, 0.f, 0.f);
                    ob = make_float4(0.f, 0.f, 0.f, 0.f);
                }
                float* orow = out_feat + (size_t)gr * COUT;
                ((float4*)orow)[cb]      = oa;
                ((float4*)orow)[16 + cb] = ob;
            }
        }
    }

    // --- coords (src/valid already in smem) ---------------------------------
    if (tid < TR) {
        int gr = base + tid;
        if (gr < totalRows) {
            int b   = gr >> KP_LOG2;
            int src = src_s[tid];
            float col0 = (b < B - 1) ? (float)(b + 1) : 0.f;   // reference quirk
            float4 o;
            o.x = col0;
            if (val_s[tid]) {
                o.y = cc[(size_t)src * 3 + 0];
                o.z = cc[(size_t)src * 3 + 1];
                o.w = cc[(size_t)src * 3 + 2];
            } else {
                o.y = 0.f; o.z = 0.f; o.w = 0.f;
            }
            ((float4*)out_coor)[gr] = o;
        }
    }
}

extern "C" void kernel_launch(void* const* d_in, const int* in_sizes, int n_in,
                              void* d_out, int out_size)
{
    const float* feat     = (const float*)d_in[0];
    const float* cc       = (const float*)d_in[1];
    const int*   vidx     = (const int*)d_in[2];     // int32 (JAX x64 disabled)
    const int*   num_list = (const int*)d_in[3];
    const float* W        = (const float*)d_in[4];
    const float* gamma    = (const float*)d_in[5];
    const float* beta     = (const float*)d_in[6];

    int Nfeat = in_sizes[0] / CIN;   // 200000
    int M     = in_sizes[1] / 3;     // 40000
    int B     = in_sizes[3];         // 4
    int totalRows = B * KP;          // 8192

    float* out_feat = (float*)d_out;
    float* out_coor = out_feat + (size_t)totalRows * COUT;

    int gridMain = (totalRows + TR - 1) / TR;   // 128 CTAs
    fused_gather_gemm_ln<<<gridMain, NT>>>(feat, vidx, W, gamma, beta, num_list,
                                           cc, out_feat, out_coor,
                                           Nfeat, M, B, totalRows);
}

// round 9
// speedup vs baseline: 3.0551x; 3.0551x over previous
#include <cuda_runtime.h>
#include <cuda_bf16.h>
#include <stdint.h>

// ---------------------------------------------------------------------------
// DynamicPointConvBackBone, mma.sync bf16-split edition (sm_103 baseline PTX;
// tcgen05 unavailable: harness compiles through compute_103 non-'a').
// D[8192,128] = gather(A)[8192,1728] @ W[1728,128]:
//   A = Ah + Al, W = Wh + Wl (bf16);  D ~= Ah*Wh + Ah*Wl + Al*Wh  (f32 accum)
// 128 CTAs x 256 thr, CTA tile 64 rows x 128 cols, chunk = 1 neighbor (K=64).
// W pre-swizzled+split by prep kernel -> one cp.async.bulk per 16KB chunk.
// A gathered via LDG + cvt + swizzled STS, double-buffered.
// Warp tile 32x32 (2M x 4N), mma.sync.m16n8k16, f32 regs; smem-spill LayerNorm.
// ---------------------------------------------------------------------------

#define K3      27
#define CIN     64
#define COUT    128
#define KP      2048
#define KP_LOG2 11
#define TR      64
#define NT      256
#define EPS     1e-3f

#define SW128(o) ((o) ^ (((o) >> 3) & 0x70))

// ---- dynamic smem layout (bytes) ----
#define SM_MBAR   0        // 2 x 8B
#define SM_NL     32
#define SM_SRC    64       // 64 ints
#define SM_VAL    320
#define SM_GAMMA  576      // 128 f32
#define SM_BETA   1088
#define SM_IDX    1600     // 64*27*4 = 6912
#define SM_STAGE0 16384
#define STG_SZ    49152    // Ahi 8K | Alo 8K | Bhi 16K | Blo 16K
#define OFF_AHI   0
#define OFF_ALO   8192
#define OFF_BHI   16384
#define OFF_BLO   32768
#define SMEM_TOTAL (SM_STAGE0 + 2 * STG_SZ)   // 114688

// W packed: [chunk][split][16KB pre-swizzled bf16 tile: n rows x 64 k]
__device__ __align__(1024) uint8_t g_Wpk[K3][2][16384];

__device__ __forceinline__ uint32_t smem_u32(const void* p) {
    uint32_t a;
    asm("{ .reg .u64 t; cvta.to.shared.u64 t, %1; cvt.u32.u64 %0, t; }"
        : "=r"(a) : "l"(p));
    return a;
}
__device__ __forceinline__ void mbar_init(uint32_t a, uint32_t cnt) {
    asm volatile("mbarrier.init.shared.b64 [%0], %1;" :: "r"(a), "r"(cnt) : "memory");
}
__device__ __forceinline__ void mbar_inval(uint32_t a) {
    asm volatile("mbarrier.inval.shared.b64 [%0];" :: "r"(a) : "memory");
}
__device__ __forceinline__ void mbar_expect_tx(uint32_t a, uint32_t tx) {
    asm volatile("mbarrier.arrive.expect_tx.shared.b64 _, [%0], %1;"
                 :: "r"(a), "r"(tx) : "memory");
}
__device__ __forceinline__ void mbar_wait(uint32_t a, uint32_t parity) {
    asm volatile(
        "{\n\t.reg .pred P;\n\t"
        "W_%=:\n\t"
        "mbarrier.try_wait.parity.acquire.cta.shared::cta.b64 P, [%0], %1, 0x989680;\n\t"
        "@P bra D_%=;\n\t"
        "bra.uni W_%=;\n\t"
        "D_%=:\n\t}"
        :: "r"(a), "r"(parity) : "memory");
}
__device__ __forceinline__ void bulk_g2s(uint32_t dst, const void* src,
                                         uint32_t bytes, uint32_t mbar) {
    asm volatile(
        "cp.async.bulk.shared::cta.global.mbarrier::complete_tx::bytes "
        "[%0], [%1], %2, [%3];"
        :: "r"(dst), "l"(src), "r"(bytes), "r"(mbar) : "memory");
}
#define LDSM4(r0, r1, r2, r3, addr) \
    asm volatile("ldmatrix.sync.aligned.m8n8.x4.shared.b16 {%0,%1,%2,%3}, [%4];" \
                 : "=r"(r0), "=r"(r1), "=r"(r2), "=r"(r3) : "r"(addr))
#define MMA16816(d, a, b) \
    asm volatile("mma.sync.aligned.m16n8k16.row.col.f32.bf16.bf16.f32 " \
                 "{%0,%1,%2,%3}, {%4,%5,%6,%7}, {%8,%9}, {%0,%1,%2,%3};" \
                 : "+f"((d)[0]), "+f"((d)[1]), "+f"((d)[2]), "+f"((d)[3]) \
                 : "r"((a)[0]), "r"((a)[1]), "r"((a)[2]), "r"((a)[3]), \
                   "r"((b)[0]), "r"((b)[1]))

// split f32 pair -> bf16x2 hi + bf16x2 lo (lower half = first element)
__device__ __forceinline__ void cvt_split(float a, float b, uint32_t& hi, uint32_t& lo) {
    asm("cvt.rn.bf16x2.f32 %0, %1, %2;" : "=r"(hi) : "f"(b), "f"(a));
    float ha = __uint_as_float(hi << 16);
    float hb = __uint_as_float(hi & 0xffff0000u);
    float da = a - ha, db = b - hb;
    asm("cvt.rn.bf16x2.f32 %0, %1, %2;" : "=r"(lo) : "f"(db), "f"(da));
}

// ---------------- prep: W[k][n] f32 -> g_Wpk[c][sp][SW128(n*128+k*2)] --------
__global__ void prep_w(const float* __restrict__ W) {
    int i = blockIdx.x * blockDim.x + threadIdx.x;
    if (i >= K3 * 64 * COUT) return;
    int n = i & 127;
    int k = (i >> 7) & 63;
    int c = i >> 13;
    float w = W[(size_t)(c * 64 + k) * COUT + n];
    __nv_bfloat16 h = __float2bfloat16(w);
    __nv_bfloat16 l = __float2bfloat16(w - __bfloat162float(h));
    uint32_t off = SW128((uint32_t)(n * 128 + k * 2));
    *(__nv_bfloat16*)(&g_Wpk[c][0][off]) = h;
    *(__nv_bfloat16*)(&g_Wpk[c][1][off]) = l;
}

// ---------------- main fused kernel ----------------
__global__ __launch_bounds__(NT, 1)
void fused_mma_ln(const float* __restrict__ feat,
                  const int* __restrict__ vidx,
                  const float* __restrict__ gamma,
                  const float* __restrict__ beta,
                  const int* __restrict__ num_list,
                  const float* __restrict__ cc,
                  float* __restrict__ out_feat,
                  float* __restrict__ out_coor,
                  int Nfeat, int M, int B, int totalRows)
{
    extern __shared__ char dsm[];
    const uint32_t smb = smem_u32(dsm);
    const int tid  = threadIdx.x;
    const int wid  = tid >> 5;
    const int lane = tid & 31;
    const int base = blockIdx.x * TR;

    int* const nl_s  = (int*)(dsm + SM_NL);
    int* const src_s = (int*)(dsm + SM_SRC);
    int* const val_s = (int*)(dsm + SM_VAL);
    int* const idx_s = (int*)(dsm + SM_IDX);

    if (tid == 0) {
        mbar_init(smb + SM_MBAR + 0, 1);
        mbar_init(smb + SM_MBAR + 8, 1);
        #pragma unroll 4
        for (int i = 0; i < B && i < 8; ++i) nl_s[i] = num_list[i];
    }
    if (tid < COUT) {
        ((float*)(dsm + SM_GAMMA))[tid] = gamma[tid];
        ((float*)(dsm + SM_BETA))[tid]  = beta[tid];
    }
    __syncthreads();

    // --- per-row source voxel + validity ------------------------------------
    if (tid < TR) {
        int gr = base + tid;
        int b = gr >> KP_LOG2;
        int j = gr & (KP - 1);
        int off = 0;
        #pragma unroll 4
        for (int i = 0; i < b; ++i) off += nl_s[i];
        int nl = nl_s[b];
        int src = off + j;
        if (src > M - 1) src = M - 1;
        if (src < 0)     src = 0;
        src_s[tid] = src;
        val_s[tid] = (j < nl) ? 1 : 0;
    }
    __syncthreads();

    // --- neighbor indices ---------------------------------------------------
    for (int e = tid; e < TR * K3; e += NT) {
        int r = e / K3, k = e - r * K3;
        int raw = vidx[(size_t)src_s[r] * K3 + k];
        int v = raw;
        if (raw < 0) v = -1;
        else if (v > Nfeat - 1) v = Nfeat - 1;
        idx_s[e] = v;
    }
    __syncthreads();

    // --- kick off B bulk copies for chunks 0,1 ------------------------------
    if (tid == 0) {
        #pragma unroll
        for (int s = 0; s < 2; ++s) {
            uint32_t mb = smb + SM_MBAR + s * 8;
            uint32_t bd = smb + SM_STAGE0 + s * STG_SZ;
            mbar_expect_tx(mb, 32768);
            bulk_g2s(bd + OFF_BHI, g_Wpk[s][0], 16384, mb);
            bulk_g2s(bd + OFF_BLO, g_Wpk[s][1], 16384, mb);
        }
    }

    // --- A gather mapping: row = tid>>2, quarter q = tid&3 (16 channels) ----
    const int g_row = tid >> 2;
    const int g_q   = tid & 3;

    float4 areg[4];
    {
        int fid = idx_s[g_row * K3 + 0];
        const float4* src = (fid >= 0)
            ? (const float4*)(feat + (size_t)fid * CIN + g_q * 16) : nullptr;
        #pragma unroll
        for (int i = 0; i < 4; ++i)
            areg[i] = src ? src[i] : make_float4(0.f, 0.f, 0.f, 0.f);
    }

    // --- warp tiling: 2M x 4N, warp tile 32 rows x 32 cols ------------------
    const int wm = wid & 1;           // rows wm*32 .. +31
    const int wn = wid >> 1;          // cols wn*32 .. +31
    const int m_  = lane >> 3;        // ldmatrix matrix id
    const int ri  = lane & 7;

    // A frag addressing: row = wm*32 + mt*16 + (m&1)*8 + ri ; kb = ks*32 + (m>>1)*16
    uint32_t arow[2], axor[2];
    #pragma unroll
    for (int mt = 0; mt < 2; ++mt) {
        uint32_t rp = (uint32_t)(wm * 32 + mt * 16 + (m_ & 1) * 8 + ri) * 128;
        arow[mt] = rp;
        axor[mt] = (rp >> 3) & 0x70;
    }
    const uint32_t akc = ((lane >> 4) & 1) * 16;
    // B frag addressing: n = wn*32 + pt*16 + (m>>1)*8 + ri ; kb = ks*32 + (m&1)*16
    uint32_t brow[2], bxor[2];
    #pragma unroll
    for (int pt = 0; pt < 2; ++pt) {
        uint32_t rp = (uint32_t)(wn * 32 + pt * 16 + ((lane >> 4) & 1) * 8 + ri) * 128;
        brow[pt] = rp;
        bxor[pt] = (rp >> 3) & 0x70;
    }
    const uint32_t bkc = ((lane >> 3) & 1) * 16;

    float acc[2][4][4];               // [mt][nt][reg]
    #pragma unroll
    for (int mt = 0; mt < 2; ++mt)
        #pragma unroll
        for (int nt = 0; nt < 4; ++nt)
            #pragma unroll
            for (int r = 0; r < 4; ++r) acc[mt][nt][r] = 0.f;

    for (int c = 0; c < K3; ++c) {
        const int s = c & 1;
        const uint32_t stg = smb + SM_STAGE0 + s * STG_SZ;

        // STS A(c) from prefetch regs: bf16 hi/lo, swizzled
        {
            uint32_t h[8], l[8];
            #pragma unroll
            for (int i = 0; i < 4; ++i) {
                cvt_split(areg[i].x, areg[i].y, h[2*i],   l[2*i]);
                cvt_split(areg[i].z, areg[i].w, h[2*i+1], l[2*i+1]);
            }
            uint32_t o0 = SW128((uint32_t)(g_row * 128 + g_q * 32));
            uint32_t o1 = SW128((uint32_t)(g_row * 128 + g_q * 32 + 16));
            *(uint4*)(dsm + SM_STAGE0 + s * STG_SZ + OFF_AHI + o0) =
                make_uint4(h[0], h[1], h[2], h[3]);
            *(uint4*)(dsm + SM_STAGE0 + s * STG_SZ + OFF_AHI + o1) =
                make_uint4(h[4], h[5], h[6], h[7]);
            *(uint4*)(dsm + SM_STAGE0 + s * STG_SZ + OFF_ALO + o0) =
                make_uint4(l[0], l[1], l[2], l[3]);
            *(uint4*)(dsm + SM_STAGE0 + s * STG_SZ + OFF_ALO + o1) =
                make_uint4(l[4], l[5], l[6], l[7]);
        }
        // prefetch A regs for chunk c+1
        if (c + 1 < K3) {
            int fid = idx_s[g_row * K3 + c + 1];
            const float4* src = (fid >= 0)
                ? (const float4*)(feat + (size_t)fid * CIN + g_q * 16) : nullptr;
            #pragma unroll
            for (int i = 0; i < 4; ++i)
                areg[i] = src ? src[i] : make_float4(0.f, 0.f, 0.f, 0.f);
        }
        __syncthreads();                       // A(c) visible to all warps
        mbar_wait(smb + SM_MBAR + s * 8, (c >> 1) & 1);   // B(c) arrived

        // compute: 4 k16-steps
        const uint32_t Ah = stg + OFF_AHI, Al = stg + OFF_ALO;
        const uint32_t Bh = stg + OFF_BHI, Bl = stg + OFF_BLO;
        #pragma unroll
        for (int ks = 0; ks < 4; ++ks) {
            uint32_t ah[2][4], al[2][4], bh[4][2], bl[4][2];
            const uint32_t akb = ks * 32 + akc;
            const uint32_t bkb = ks * 32 + bkc;
            #pragma unroll
            for (int mt = 0; mt < 2; ++mt) {
                LDSM4(ah[mt][0], ah[mt][1], ah[mt][2], ah[mt][3],
                      Ah + arow[mt] + (akb ^ axor[mt]));
                LDSM4(al[mt][0], al[mt][1], al[mt][2], al[mt][3],
                      Al + arow[mt] + (akb ^ axor[mt]));
            }
            #pragma unroll
            for (int pt = 0; pt < 2; ++pt) {
                LDSM4(bh[2*pt][0], bh[2*pt][1], bh[2*pt+1][0], bh[2*pt+1][1],
                      Bh + brow[pt] + (bkb ^ bxor[pt]));
                LDSM4(bl[2*pt][0], bl[2*pt][1], bl[2*pt+1][0], bl[2*pt+1][1],
                      Bl + brow[pt] + (bkb ^ bxor[pt]));
            }
            #pragma unroll
            for (int mt = 0; mt < 2; ++mt)
                #pragma unroll
                for (int nt = 0; nt < 4; ++nt) {
                    MMA16816(acc[mt][nt], ah[mt], bh[nt]);
                    MMA16816(acc[mt][nt], ah[mt], bl[nt]);
                    MMA16816(acc[mt][nt], al[mt], bh[nt]);
                }
        }
        __syncthreads();                       // stage s free
        if (tid == 0 && c + 2 < K3) {          // refill stage s with chunk c+2
            uint32_t mb = smb + SM_MBAR + s * 8;
            mbar_expect_tx(mb, 32768);
            bulk_g2s(stg + OFF_BHI, g_Wpk[c + 2][0], 16384, mb);
            bulk_g2s(stg + OFF_BLO, g_Wpk[c + 2][1], 16384, mb);
        }
    }

    // --- spill accumulators to smem (reuse stage0: 32KB) --------------------
    float* const Red = (float*)(dsm + SM_STAGE0);
    {
        #pragma unroll
        for (int mt = 0; mt < 2; ++mt) {
            int r0 = wm * 32 + mt * 16 + (lane >> 2);
            #pragma unroll
            for (int nt = 0; nt < 4; ++nt) {
                int cbase = wn * 32 + nt * 8 + (lane & 3) * 2;
                *(float2*)(Red + r0 * COUT + cbase) =
                    make_float2(acc[mt][nt][0], acc[mt][nt][1]);
                *(float2*)(Red + (r0 + 8) * COUT + cbase) =
                    make_float2(acc[mt][nt][2], acc[mt][nt][3]);
            }
        }
    }
    __syncthreads();

    // --- LayerNorm + ReLU: row = tid>>2, quad q = tid&3 (32 cols) -----------
    {
        const int row = tid >> 2;
        const int q   = tid & 3;
        const float* rrow = Red + row * COUT + q * 32;
        float4 v[8];
        float s = 0.f, sq = 0.f;
        #pragma unroll
        for (int i = 0; i < 8; ++i) {
            v[i] = ((const float4*)rrow)[i];
            s  += v[i].x + v[i].y + v[i].z + v[i].w;
            sq += v[i].x*v[i].x + v[i].y*v[i].y + v[i].z*v[i].z + v[i].w*v[i].w;
        }
        s  += __shfl_xor_sync(0xffffffffu, s, 1);
        sq += __shfl_xor_sync(0xffffffffu, sq, 1);
        s  += __shfl_xor_sync(0xffffffffu, s, 2);
        sq += __shfl_xor_sync(0xffffffffu, sq, 2);
        float mu  = s * (1.f / COUT);
        float var = sq * (1.f / COUT) - mu * mu;
        float inv = rsqrtf(var + EPS);
        int valid = val_s[row];
        int gr = base + row;
        const float* gs = (const float*)(dsm + SM_GAMMA) + q * 32;
        const float* bs = (const float*)(dsm + SM_BETA)  + q * 32;
        float* orow = out_feat + (size_t)gr * COUT + q * 32;
        #pragma unroll
        for (int i = 0; i < 8; ++i) {
            float4 o;
            o.x = fmaxf(0.f, (v[i].x - mu) * inv * gs[4*i+0] + bs[4*i+0]);
            o.y = fmaxf(0.f, (v[i].y - mu) * inv * gs[4*i+1] + bs[4*i+1]);
            o.z = fmaxf(0.f, (v[i].z - mu) * inv * gs[4*i+2] + bs[4*i+2]);
            o.w = fmaxf(0.f, (v[i].w - mu) * inv * gs[4*i+3] + bs[4*i+3]);
            if (!valid) o = make_float4(0.f, 0.f, 0.f, 0.f);
            ((float4*)orow)[i] = o;
        }
    }

    // --- coords (col0 unconditional per reference quirk; xyz masked) --------
    if (tid < TR) {
        int gr = base + tid;
        int b  = gr >> KP_LOG2;
        int src = src_s[tid];
        float col0 = (b < B - 1) ? (float)(b + 1) : 0.f;
        float4 o;
        o.x = col0;
        if (val_s[tid]) {
            o.y = cc[(size_t)src * 3 + 0];
            o.z = cc[(size_t)src * 3 + 1];
            o.w = cc[(size_t)src * 3 + 2];
        } else {
            o.y = 0.f; o.z = 0.f; o.w = 0.f;
        }
        ((float4*)out_coor)[gr] = o;
    }

    __syncthreads();
    if (tid == 0) { mbar_inval(smb + SM_MBAR + 0); mbar_inval(smb + SM_MBAR + 8); }
}

extern "C" void kernel_launch(void* const* d_in, const int* in_sizes, int n_in,
                              void* d_out, int out_size)
{
    const float* feat     = (const float*)d_in[0];
    const float* cc       = (const float*)d_in[1];
    const int*   vidx     = (const int*)d_in[2];     // int32 (JAX x64 disabled)
    const int*   num_list = (const int*)d_in[3];
    const float* W        = (const float*)d_in[4];
    const float* gamma    = (const float*)d_in[5];
    const float* beta     = (const float*)d_in[6];

    int Nfeat = in_sizes[0] / CIN;   // 200000
    int M     = in_sizes[1] / 3;     // 40000
    int B     = in_sizes[3];         // 4
    int totalRows = B * KP;          // 8192

    float* out_feat = (float*)d_out;
    float* out_coor = out_feat + (size_t)totalRows * COUT;

    cudaFuncSetAttribute(fused_mma_ln,
                         cudaFuncAttributeMaxDynamicSharedMemorySize, SMEM_TOTAL);

    prep_w<<<(K3 * 64 * COUT + 255) / 256, 256>>>(W);
    fused_mma_ln<<<totalRows / TR, NT, SMEM_TOTAL>>>(feat, vidx, gamma, beta,
                                                     num_list, cc, out_feat,
                                                     out_coor, Nfeat, M, B,
                                                     totalRows);
}